// round 8
// baseline (speedup 1.0000x reference)
#include <cuda_runtime.h>
#include <math.h>

// ---------------- problem constants ----------------
#define L    12000
#define IN_  1024
#define D_   128
#define ED_  256
#define NST  16
#define DTD  8
#define KC   4
#define NLAY 2
#define EPSV 1e-5f

// chunked scan config: 296 chunks of 41 (296 = 2*148 SMs)
#define CH  296
#define LC  41

// pooled partial blocks
#define PB  96

// ---------------- device scratch (static, no allocation) ----------------
__device__ float g_h    [L * D_];        // residual stream
__device__ float g_hn   [L * D_];        // normed stream
__device__ float g_xz   [L * 2 * ED_];   // inproj out (xb | z); reused for att hidden
__device__ float g_xc   [L * ED_];       // conv+silu out
__device__ float g_dbl  [L * 40];        // xproj out (dlt | B | C)
__device__ float g_delta[L * ED_];       // softplus(dt)
__device__ float g_y    [L * ED_];       // scan output (gated)
__device__ float g_Aprod[CH * ED_ * NST];
__device__ float g_Bacc [CH * ED_ * NST];
__device__ float g_Hinit[CH * ED_ * NST];
__device__ float g_att  [L];
__device__ float g_part [PB * D_];

// ---------------- packed f32x2 helpers ----------------
__device__ __forceinline__ unsigned long long pack2_dup(float v) {
    unsigned long long r;
    asm("mov.b64 %0, {%1, %1};" : "=l"(r) : "f"(v));
    return r;
}
__device__ __forceinline__ void fma2(unsigned long long& d, unsigned long long a,
                                     unsigned long long b) {
    asm("fma.rn.f32x2 %0, %1, %2, %0;" : "+l"(d) : "l"(a), "l"(b));
}
__device__ __forceinline__ void unpack2(unsigned long long v, float& lo, float& hi) {
    asm("mov.b64 {%0, %1}, %2;" : "=f"(lo), "=f"(hi) : "l"(v));
}

// ---------------- high-throughput SGEMM with packed FFMA2 ----------------
// C[M,N] = act(A[M,K] @ W[K,N] (+bias)), optional +=
// Tile: BMv x BNv, 256 threads, micro-tile TMv x TNv per thread.
// Inner product uses fma.rn.f32x2 with lanes = (row m, row m+1):
//   a2 = {A[m],A[m+1]} (native LDS.64 from transposed A tile)
//   b2 = {W[n],W[n]}   (packed once per kk per n)
#define BK_ 16

template<int BMv, int BNv, int TMv, int TNv>
__global__ __launch_bounds__(256, 2)
void gemm2_kernel(const float* __restrict__ A, const float* __restrict__ W,
                  const float* __restrict__ bias, float* __restrict__ C,
                  int M, int K, int N, int act, int acc)
{
    constexpr int THREADS = (BMv / TMv) * (BNv / TNv);   // 256
    static_assert(THREADS == 256, "256 threads");
    constexpr int NTX = BNv / TNv;
    constexpr int AF4 = BMv * BK_ / 4;                   // float4 count, A tile
    constexpr int APT = AF4 / THREADS;
    constexpr int WF4 = BK_ * BNv / 4;
    constexpr int WPT = (WF4 + THREADS - 1) / THREADS;

    __shared__ float As[BK_][BMv];   // transposed: As[k][m]
    __shared__ float Ws[BK_][BNv];   // natural:    Ws[k][n]

    const int tid  = threadIdx.x;
    const int row0 = blockIdx.y * BMv;
    const int col0 = blockIdx.x * BNv;
    const int tx = tid % NTX;
    const int ty = tid / NTX;

    unsigned long long acc2[TMv / 2][TNv];
    #pragma unroll
    for (int i = 0; i < TMv / 2; i++)
        #pragma unroll
        for (int j = 0; j < TNv; j++) acc2[i][j] = 0ull;

    float4 aldg[APT], wldg[WPT];

    auto ldgA = [&](int k0) {
        #pragma unroll
        for (int p = 0; p < APT; p++) {
            const int f = tid + p * THREADS;
            const int r = f >> 2;          // row in tile (BK_/4 == 4)
            const int kq = f & 3;
            const int gr = row0 + r;
            if (gr < M)
                aldg[p] = *reinterpret_cast<const float4*>(&A[(size_t)gr * K + k0 + kq * 4]);
            else
                aldg[p] = make_float4(0.f, 0.f, 0.f, 0.f);
        }
    };
    auto stsA = [&]() {
        #pragma unroll
        for (int p = 0; p < APT; p++) {
            const int f = tid + p * THREADS;
            const int r = f >> 2;
            const int kq = f & 3;
            As[kq * 4 + 0][r] = aldg[p].x;
            As[kq * 4 + 1][r] = aldg[p].y;
            As[kq * 4 + 2][r] = aldg[p].z;
            As[kq * 4 + 3][r] = aldg[p].w;
        }
    };
    auto ldgW = [&](int k0) {
        #pragma unroll
        for (int p = 0; p < WPT; p++) {
            const int f = tid + p * THREADS;
            if (f < WF4) {
                const int k  = f / (BNv / 4);
                const int nq = f % (BNv / 4);
                const int gn0 = col0 + nq * 4;
                if (gn0 + 3 < N) {
                    wldg[p] = *reinterpret_cast<const float4*>(&W[(size_t)(k0 + k) * N + gn0]);
                } else {
                    float v[4];
                    #pragma unroll
                    for (int j = 0; j < 4; j++)
                        v[j] = (gn0 + j < N) ? W[(size_t)(k0 + k) * N + gn0 + j] : 0.f;
                    wldg[p] = make_float4(v[0], v[1], v[2], v[3]);
                }
            }
        }
    };
    auto stsW = [&]() {
        #pragma unroll
        for (int p = 0; p < WPT; p++) {
            const int f = tid + p * THREADS;
            if (f < WF4) {
                const int k  = f / (BNv / 4);
                const int nq = f % (BNv / 4);
                *reinterpret_cast<float4*>(&Ws[k][nq * 4]) = wldg[p];
            }
        }
    };

    // prologue
    ldgA(0); ldgW(0);
    stsA(); stsW();
    __syncthreads();

    const int KT = K / BK_;
    for (int kt = 0; kt < KT; kt++) {
        if (kt + 1 < KT) { ldgA((kt + 1) * BK_); ldgW((kt + 1) * BK_); }

        #pragma unroll
        for (int kk = 0; kk < BK_; kk++) {
            // a pairs: native 8-byte loads from transposed A tile
            unsigned long long a2[TMv / 2];
            const unsigned long long* arow =
                reinterpret_cast<const unsigned long long*>(&As[kk][ty * TMv]);
            #pragma unroll
            for (int ip = 0; ip < TMv / 2; ip++) a2[ip] = arow[ip];
            // W frag + broadcast-pack
            float wf[TNv];
            #pragma unroll
            for (int j4 = 0; j4 < TNv / 4; j4++) {
                const float4 w4 =
                    *reinterpret_cast<const float4*>(&Ws[kk][tx * TNv + j4 * 4]);
                wf[j4 * 4 + 0] = w4.x; wf[j4 * 4 + 1] = w4.y;
                wf[j4 * 4 + 2] = w4.z; wf[j4 * 4 + 3] = w4.w;
            }
            unsigned long long w2[TNv];
            #pragma unroll
            for (int j = 0; j < TNv; j++) w2[j] = pack2_dup(wf[j]);
            #pragma unroll
            for (int ip = 0; ip < TMv / 2; ip++)
                #pragma unroll
                for (int j = 0; j < TNv; j++)
                    fma2(acc2[ip][j], a2[ip], w2[j]);
        }
        __syncthreads();
        if (kt + 1 < KT) { stsA(); stsW(); __syncthreads(); }
    }

    // epilogue
    #pragma unroll
    for (int ip = 0; ip < TMv / 2; ip++) {
        const int m0 = row0 + ty * TMv + ip * 2;
        #pragma unroll
        for (int j = 0; j < TNv; j++) {
            const int n = col0 + tx * TNv + j;
            if (n >= N) continue;
            float v0, v1;
            unpack2(acc2[ip][j], v0, v1);
            const float bb = bias ? bias[n] : 0.f;
            v0 += bb; v1 += bb;
            if (act == 1) {
                v0 = 0.5f * v0 * (1.f + erff(v0 * 0.70710678118654752f));
                v1 = 0.5f * v1 * (1.f + erff(v1 * 0.70710678118654752f));
            } else if (act == 2) {
                v0 = tanhf(v0); v1 = tanhf(v1);
            }
            if (m0 < M) {
                if (acc) C[(size_t)m0 * N + n] += v0;
                else     C[(size_t)m0 * N + n]  = v0;
            }
            if (m0 + 1 < M) {
                if (acc) C[(size_t)(m0 + 1) * N + n] += v1;
                else     C[(size_t)(m0 + 1) * N + n]  = v1;
            }
        }
    }
}

// ---------------- row norms (D=128, one row per 128-thread block) ----------------
__global__ void rmsnorm_kernel(const float* __restrict__ in, const float* __restrict__ w,
                               float* __restrict__ out)
{
    const int row = blockIdx.x, d = threadIdx.x;
    const float v = in[row * D_ + d];
    float s = v * v;
    #pragma unroll
    for (int o = 16; o; o >>= 1) s += __shfl_xor_sync(0xffffffffu, s, o);
    __shared__ float sm[4];
    __shared__ float scale;
    if ((d & 31) == 0) sm[d >> 5] = s;
    __syncthreads();
    if (d == 0) scale = rsqrtf((sm[0] + sm[1] + sm[2] + sm[3]) * (1.f / D_) + EPSV);
    __syncthreads();
    out[row * D_ + d] = v * scale * w[d];
}

__global__ void layernorm_kernel(const float* __restrict__ in, const float* __restrict__ w,
                                 const float* __restrict__ b, float* __restrict__ out)
{
    const int row = blockIdx.x, d = threadIdx.x;
    const float v = in[row * D_ + d];
    float s = v, sq = v * v;
    #pragma unroll
    for (int o = 16; o; o >>= 1) {
        s  += __shfl_xor_sync(0xffffffffu, s,  o);
        sq += __shfl_xor_sync(0xffffffffu, sq, o);
    }
    __shared__ float sm0[4], sm1[4];
    __shared__ float mean, inv;
    if ((d & 31) == 0) { sm0[d >> 5] = s; sm1[d >> 5] = sq; }
    __syncthreads();
    if (d == 0) {
        float S = sm0[0] + sm0[1] + sm0[2] + sm0[3];
        float Q = sm1[0] + sm1[1] + sm1[2] + sm1[3];
        float m = S * (1.f / D_);
        float var = Q * (1.f / D_) - m * m;
        mean = m;
        inv = rsqrtf(var + EPSV);
    }
    __syncthreads();
    out[row * D_ + d] = (v - mean) * inv * w[d] + b[d];
}

// ---------------- depthwise causal conv (K=4) + silu ----------------
__global__ void conv_silu_kernel(const float* __restrict__ cw, const float* __restrict__ cb)
{
    const int t = blockIdx.x, e = threadIdx.x;
    float s = cb[e];
    #pragma unroll
    for (int j = 0; j < KC; j++) {
        int tt = t - (KC - 1) + j;
        if (tt >= 0) s = fmaf(g_xz[(size_t)tt * (2 * ED_) + e], cw[e * KC + j], s);
    }
    const float sg = 1.f / (1.f + __expf(-s));
    g_xc[(size_t)t * ED_ + e] = s * sg;
}

// ---------------- delta = softplus(dlt @ dt_w + dt_b) (K=8) ----------------
#define DTROWS 32
__global__ void dt_kernel(const float* __restrict__ dtw, const float* __restrict__ dtb)
{
    const int t0 = blockIdx.x * DTROWS;
    const int e = threadIdx.x;
    __shared__ float sd[DTROWS][DTD];
    for (int idx = e; idx < DTROWS * DTD; idx += ED_) {
        int r = idx >> 3, k = idx & 7;
        int t = t0 + r;
        sd[r][k] = (t < L) ? g_dbl[(size_t)t * 40 + k] : 0.f;
    }
    __syncthreads();
    float w[DTD];
    #pragma unroll
    for (int k = 0; k < DTD; k++) w[k] = dtw[k * ED_ + e];
    const float b = dtb[e];
    for (int r = 0; r < DTROWS; r++) {
        int t = t0 + r;
        if (t >= L) break;
        float s = b;
        #pragma unroll
        for (int k = 0; k < DTD; k++) s = fmaf(sd[r][k], w[k], s);
        float sp = (s > 0.f) ? (s + log1pf(__expf(-s))) : log1pf(__expf(s));
        g_delta[(size_t)t * ED_ + e] = sp;
    }
}

// ---------------- chunked selective scan ----------------
// phase 1: per-chunk (prod dA, local scan with h0=0)
__global__ void scan_pass1(const float* __restrict__ alog)
{
    const int e = threadIdx.x;            // 0..255
    const int chunk = blockIdx.x;
    const int t0 = chunk * LC;
    const int tend = min(t0 + LC, L);
    const int nt = tend - t0;

    __shared__ float sB[LC][NST];
    for (int idx = e; idx < nt * NST; idx += ED_) {
        int tt = idx >> 4, n = idx & 15;
        sB[tt][n] = g_dbl[(size_t)(t0 + tt) * 40 + DTD + n];
    }
    __syncthreads();

    float Areg[NST];
    #pragma unroll
    for (int n = 0; n < NST; n++) Areg[n] = -__expf(alog[e * NST + n]);

    float h[NST], ap[NST];
    #pragma unroll
    for (int n = 0; n < NST; n++) { h[n] = 0.f; ap[n] = 1.f; }

    for (int tt = 0; tt < nt; tt++) {
        const int t = t0 + tt;
        const float d = g_delta[(size_t)t * ED_ + e];
        const float x = g_xc[(size_t)t * ED_ + e];
        const float dx = d * x;
        #pragma unroll
        for (int n = 0; n < NST; n++) {
            const float a = __expf(d * Areg[n]);
            h[n] = fmaf(a, h[n], dx * sB[tt][n]);
            ap[n] *= a;
        }
    }
    const size_t base = (size_t)chunk * (ED_ * NST) + e * NST;
    #pragma unroll
    for (int n = 0; n < NST; n++) {
        g_Aprod[base + n] = ap[n];
        g_Bacc [base + n] = h[n];
    }
}

// phase 2: sequential combine over chunks, per channel (4096 channels)
__global__ void scan_pass2()
{
    const int c = blockIdx.x * blockDim.x + threadIdx.x;  // 0..4095
    float s = 0.f;
    for (int k = 0; k < CH; k++) {
        const size_t idx = (size_t)k * (ED_ * NST) + c;
        g_Hinit[idx] = s;
        s = fmaf(g_Aprod[idx], s, g_Bacc[idx]);
    }
}

// phase 3: replay with correct h0, fused D-skip + silu(z) gate -> g_y
__global__ void scan_pass3(const float* __restrict__ alog, const float* __restrict__ dp)
{
    const int e = threadIdx.x;
    const int chunk = blockIdx.x;
    const int t0 = chunk * LC;
    const int tend = min(t0 + LC, L);
    const int nt = tend - t0;
    if (nt <= 0) return;

    __shared__ float sB[LC][NST];
    __shared__ float sC[LC][NST];
    for (int idx = e; idx < nt * NST; idx += ED_) {
        int tt = idx >> 4, n = idx & 15;
        sB[tt][n] = g_dbl[(size_t)(t0 + tt) * 40 + DTD + n];
        sC[tt][n] = g_dbl[(size_t)(t0 + tt) * 40 + DTD + NST + n];
    }
    __syncthreads();

    float Areg[NST], h[NST];
    #pragma unroll
    for (int n = 0; n < NST; n++) Areg[n] = -__expf(alog[e * NST + n]);
    const size_t base = (size_t)chunk * (ED_ * NST) + e * NST;
    #pragma unroll
    for (int n = 0; n < NST; n++) h[n] = g_Hinit[base + n];

    const float dpe = dp[e];
    for (int tt = 0; tt < nt; tt++) {
        const int t = t0 + tt;
        const float d = g_delta[(size_t)t * ED_ + e];
        const float x = g_xc[(size_t)t * ED_ + e];
        const float dx = d * x;
        float y = 0.f;
        #pragma unroll
        for (int n = 0; n < NST; n++) {
            const float a = __expf(d * Areg[n]);
            h[n] = fmaf(a, h[n], dx * sB[tt][n]);
            y = fmaf(h[n], sC[tt][n], y);
        }
        y = fmaf(dpe, x, y);
        const float z = g_xz[(size_t)t * (2 * ED_) + ED_ + e];
        const float sg = 1.f / (1.f + __expf(-z));
        g_y[(size_t)t * ED_ + e] = y * (z * sg);
    }
}

// ---------------- attention score: a[t] = s1[t] . w2 + b2 ----------------
__global__ void att_score_kernel(const float* __restrict__ w2, const float* __restrict__ b2)
{
    const int row = blockIdx.x, d = threadIdx.x;  // 128 threads
    float v = g_xz[(size_t)row * D_ + d] * w2[d];
    #pragma unroll
    for (int o = 16; o; o >>= 1) v += __shfl_xor_sync(0xffffffffu, v, o);
    __shared__ float sm[4];
    if ((d & 31) == 0) sm[d >> 5] = v;
    __syncthreads();
    if (d == 0) g_att[row] = sm[0] + sm[1] + sm[2] + sm[3] + b2[0];
}

// ---------------- softmax over L (single block) ----------------
__global__ void softmax_kernel()
{
    const int tid = threadIdx.x;            // 1024 threads
    __shared__ float red[32];
    __shared__ float bmax, bsum;

    float m = -1e30f;
    for (int t = tid; t < L; t += 1024) m = fmaxf(m, g_att[t]);
    #pragma unroll
    for (int o = 16; o; o >>= 1) m = fmaxf(m, __shfl_xor_sync(0xffffffffu, m, o));
    if ((tid & 31) == 0) red[tid >> 5] = m;
    __syncthreads();
    if (tid < 32) {
        float v = red[tid];
        #pragma unroll
        for (int o = 16; o; o >>= 1) v = fmaxf(v, __shfl_xor_sync(0xffffffffu, v, o));
        if (tid == 0) bmax = v;
    }
    __syncthreads();
    const float mx = bmax;

    float s = 0.f;
    for (int t = tid; t < L; t += 1024) s += __expf(g_att[t] - mx);
    #pragma unroll
    for (int o = 16; o; o >>= 1) s += __shfl_xor_sync(0xffffffffu, s, o);
    __syncthreads();
    if ((tid & 31) == 0) red[tid >> 5] = s;
    __syncthreads();
    if (tid < 32) {
        float v = red[tid];
        #pragma unroll
        for (int o = 16; o; o >>= 1) v += __shfl_xor_sync(0xffffffffu, v, o);
        if (tid == 0) bsum = v;
    }
    __syncthreads();
    const float inv = 1.f / bsum;
    for (int t = tid; t < L; t += 1024) g_att[t] = __expf(g_att[t] - mx) * inv;
}

// ---------------- pooled = sum_t att[t] * h[t,:] (two-stage deterministic) ----------------
__global__ void pooled_part_kernel()
{
    const int b = blockIdx.x, d = threadIdx.x;   // PB blocks x 128 threads
    const int per = (L + PB - 1) / PB;
    const int t0 = b * per, t1 = min(t0 + per, L);
    float s = 0.f;
    for (int t = t0; t < t1; t++) s = fmaf(g_att[t], g_hn[(size_t)t * D_ + d], s);
    g_part[b * D_ + d] = s;
}

__global__ void final_kernel(const float* __restrict__ cls_w, const float* __restrict__ cls_b,
                             float* __restrict__ out, int out_size)
{
    const int d = threadIdx.x;  // 128
    float p = 0.f;
    for (int b = 0; b < PB; b++) p += g_part[b * D_ + d];
    float c0 = p * cls_w[d * 2 + 0];
    float c1 = p * cls_w[d * 2 + 1];
    #pragma unroll
    for (int o = 16; o; o >>= 1) {
        c0 += __shfl_xor_sync(0xffffffffu, c0, o);
        c1 += __shfl_xor_sync(0xffffffffu, c1, o);
    }
    __shared__ float s0[4], s1[4];
    if ((d & 31) == 0) { s0[d >> 5] = c0; s1[d >> 5] = c1; }
    __syncthreads();
    if (d == 0) {
        const float l0 = s0[0] + s0[1] + s0[2] + s0[3] + cls_b[0];
        const float l1 = s1[0] + s1[1] + s1[2] + s1[3] + cls_b[1];
        const float mx = fmaxf(l0, l1);
        const float e0 = expf(l0 - mx), e1 = expf(l1 - mx);
        const float den = e0 + e1;
        const float p0 = e0 / den, p1 = e1 / den;
        const float hat = (l1 > l0) ? 1.f : 0.f;
        if (out_size >= 1) out[0] = l0;
        if (out_size >= 2) out[1] = l1;
        if (out_size >= 3) out[2] = p0;
        if (out_size >= 4) out[3] = p1;
        if (out_size >= 5) out[4] = hat;
        for (int i = 5; i < out_size; i++) out[i] = 0.f;
    }
}

// ---------------- host orchestration ----------------
extern "C" void kernel_launch(void* const* d_in, const int* in_sizes, int n_in,
                              void* d_out, int out_size)
{
    const float* x        = (const float*)d_in[0];
    // d_in[1] = coords (unused by reference)
    const float* fc1_w    = (const float*)d_in[2];
    const float* fc1_b    = (const float*)d_in[3];
    const float* rms_w    = (const float*)d_in[4];
    const float* inproj_w = (const float*)d_in[5];
    const float* conv_w   = (const float*)d_in[6];
    const float* conv_b   = (const float*)d_in[7];
    const float* xproj_w  = (const float*)d_in[8];
    const float* dt_w     = (const float*)d_in[9];
    const float* dt_b     = (const float*)d_in[10];
    const float* A_log    = (const float*)d_in[11];
    const float* D_p      = (const float*)d_in[12];
    const float* outproj_w= (const float*)d_in[13];
    const float* ln_w     = (const float*)d_in[14];
    const float* ln_b     = (const float*)d_in[15];
    const float* att_w1   = (const float*)d_in[16];
    const float* att_b1   = (const float*)d_in[17];
    const float* att_w2   = (const float*)d_in[18];
    const float* att_b2   = (const float*)d_in[19];
    const float* cls_w    = (const float*)d_in[20];
    const float* cls_b    = (const float*)d_in[21];
    float* out = (float*)d_out;

    float *p_h, *p_hn, *p_xz, *p_xc, *p_dbl, *p_y;
    cudaGetSymbolAddress((void**)&p_h,  g_h);
    cudaGetSymbolAddress((void**)&p_hn, g_hn);
    cudaGetSymbolAddress((void**)&p_xz, g_xz);
    cudaGetSymbolAddress((void**)&p_xc, g_xc);
    cudaGetSymbolAddress((void**)&p_dbl,g_dbl);
    cudaGetSymbolAddress((void**)&p_y,  g_y);

    const int MT128 = (L + 127) / 128;   // 94 row tiles

    // 1) h = gelu(x @ fc1_w + fc1_b)   (N=128 -> BN=64 for 188 blocks)
    gemm2_kernel<128, 64, 8, 4><<<dim3(2, MT128), 256>>>(x, fc1_w, fc1_b, p_h,
                                                         L, IN_, D_, /*gelu*/1, 0);

    for (int layer = 0; layer < NLAY; layer++) {
        const float* ipw  = inproj_w  + (size_t)layer * D_ * 2 * ED_;
        const float* cw   = conv_w    + (size_t)layer * ED_ * KC;
        const float* cb   = conv_b    + (size_t)layer * ED_;
        const float* xpw  = xproj_w   + (size_t)layer * ED_ * 40;
        const float* dtw  = dt_w      + (size_t)layer * DTD * ED_;
        const float* dtb  = dt_b      + (size_t)layer * ED_;
        const float* alog = A_log     + (size_t)layer * ED_ * NST;
        const float* dp   = D_p       + (size_t)layer * ED_;
        const float* opw  = outproj_w + (size_t)layer * ED_ * D_;
        const float* rw   = rms_w     + (size_t)layer * D_;

        // hn = rmsnorm(h)
        rmsnorm_kernel<<<L, D_>>>(p_h, rw, p_hn);
        // xz = hn @ inproj  (L x 512)
        gemm2_kernel<128, 128, 8, 8><<<dim3(4, MT128), 256>>>(p_hn, ipw, nullptr, p_xz,
                                                              L, D_, 2 * ED_, 0, 0);
        // xc = silu(causal_conv(xb))
        conv_silu_kernel<<<L, ED_>>>(cw, cb);
        // dbl = xc @ xproj (L x 40)
        gemm2_kernel<128, 64, 8, 4><<<dim3(1, MT128), 256>>>(p_xc, xpw, nullptr, p_dbl,
                                                             L, ED_, 40, 0, 0);
        // delta = softplus(dlt @ dt_w + dt_b)
        dt_kernel<<<(L + DTROWS - 1) / DTROWS, ED_>>>(dtw, dtb);
        // chunked scan
        scan_pass1<<<CH, ED_>>>(alog);
        scan_pass2<<<16, 256>>>();
        scan_pass3<<<CH, ED_>>>(alog, dp);
        // h += y @ outproj
        gemm2_kernel<128, 64, 8, 4><<<dim3(2, MT128), 256>>>(p_y, opw, nullptr, p_h,
                                                             L, ED_, D_, 0, /*acc*/1);
    }

    // final layernorm -> hn
    layernorm_kernel<<<L, D_>>>(p_h, ln_w, ln_b, p_hn);
    // s1 = tanh(hn @ att_w1 + b1) -> reuse g_xz (stride 128)
    gemm2_kernel<128, 64, 8, 4><<<dim3(2, MT128), 256>>>(p_hn, att_w1, att_b1, p_xz,
                                                         L, D_, 128, /*tanh*/2, 0);
    att_score_kernel<<<L, D_>>>(att_w2, att_b2);
    softmax_kernel<<<1, 1024>>>();
    pooled_part_kernel<<<PB, D_>>>();
    final_kernel<<<1, D_>>>(cls_w, cls_b, out, out_size);
}

// round 9
// speedup vs baseline: 1.1389x; 1.1389x over previous
#include <cuda_runtime.h>
#include <math.h>

// ---------------- problem constants ----------------
#define L    12000
#define IN_  1024
#define D_   128
#define ED_  256
#define NST  16
#define DTD  8
#define KC   4
#define NLAY 2
#define EPSV 1e-5f

// chunked scan config: 296 chunks of 41 (296 = 2*148 SMs)
#define CH  296
#define LC  41

// pooled partial blocks
#define PB  96

// ---------------- device scratch (static, no allocation) ----------------
__device__ float g_h    [L * D_];        // residual stream
__device__ float g_hn   [L * D_];        // normed stream
__device__ float g_xz   [L * 2 * ED_];   // inproj out (xb | z); reused for att hidden
__device__ float g_xc   [L * ED_];       // conv+silu out
__device__ float g_dbl  [L * 40];        // xproj out (dlt | B | C)
__device__ float g_delta[L * ED_];       // softplus(dt)
__device__ float g_y    [L * ED_];       // scan output (gated)
__device__ float g_Aprod[CH * ED_ * NST];
__device__ float g_Bacc [CH * ED_ * NST];
__device__ float g_Hinit[CH * ED_ * NST];
__device__ float g_att  [L];
__device__ float g_part [PB * D_];

// ---------------- SGEMM: 128x64 tile, 8x4 micro-tile, double-buffered ----------------
// C[M,N] = act(A[M,K] @ W[K,N] (+bias)), optional +=
#define BM 128
#define BN 64
#define BK 16
#define TM 8
#define TN 4

__global__ __launch_bounds__(256, 2)
void gemm_kernel(const float* __restrict__ A, const float* __restrict__ W,
                 const float* __restrict__ bias, float* __restrict__ C,
                 int M, int K, int N, int act, int acc)
{
    __shared__ float As[2][BK][BM];   // transposed: As[buf][k][m]  (8 KB each)
    __shared__ float Ws[2][BK][BN];   // natural:    Ws[buf][k][n]  (4 KB each)

    const int tid  = threadIdx.x;
    const int row0 = blockIdx.y * BM;
    const int col0 = blockIdx.x * BN;
    const int tx = tid & 15;          // 16 col-groups
    const int ty = tid >> 4;          // 16 row-groups

    float accv[TM][TN];
    #pragma unroll
    for (int i = 0; i < TM; i++)
        #pragma unroll
        for (int j = 0; j < TN; j++) accv[i][j] = 0.f;

    // A tile: 128x16 floats = 512 float4 -> 2 per thread
    // mapping: f = tid + p*256; r = f>>2 (row 0..127), kq = f&3 (k-quad)
    // W tile: 16x64 = 256 float4 -> 1 per thread: k = tid>>4, nq = tid&15
    float4 aldg[2], wldg;

    auto ldgA = [&](int k0) {
        #pragma unroll
        for (int p = 0; p < 2; p++) {
            const int f = tid + p * 256;
            const int r = f >> 2;
            const int kq = f & 3;
            const int gr = row0 + r;
            if (gr < M)
                aldg[p] = *reinterpret_cast<const float4*>(&A[(size_t)gr * K + k0 + kq * 4]);
            else
                aldg[p] = make_float4(0.f, 0.f, 0.f, 0.f);
        }
    };
    auto ldgW = [&](int k0) {
        const int k  = tid >> 4;
        const int nq = tid & 15;
        const int gn0 = col0 + nq * 4;
        if (gn0 + 3 < N) {
            wldg = *reinterpret_cast<const float4*>(&W[(size_t)(k0 + k) * N + gn0]);
        } else {
            float v[4];
            #pragma unroll
            for (int j = 0; j < 4; j++)
                v[j] = (gn0 + j < N) ? W[(size_t)(k0 + k) * N + gn0 + j] : 0.f;
            wldg = make_float4(v[0], v[1], v[2], v[3]);
        }
    };
    auto sts = [&](int buf) {
        #pragma unroll
        for (int p = 0; p < 2; p++) {
            const int f = tid + p * 256;
            const int r = f >> 2;
            const int kq = f & 3;
            As[buf][kq * 4 + 0][r] = aldg[p].x;
            As[buf][kq * 4 + 1][r] = aldg[p].y;
            As[buf][kq * 4 + 2][r] = aldg[p].z;
            As[buf][kq * 4 + 3][r] = aldg[p].w;
        }
        const int k  = tid >> 4;
        const int nq = tid & 15;
        *reinterpret_cast<float4*>(&Ws[buf][k][nq * 4]) = wldg;
    };

    // prologue
    ldgA(0); ldgW(0);
    sts(0);
    __syncthreads();

    const int KT = K / BK;
    for (int kt = 0; kt < KT; kt++) {
        const int cur = kt & 1;
        if (kt + 1 < KT) { ldgA((kt + 1) * BK); ldgW((kt + 1) * BK); }

        #pragma unroll
        for (int kk = 0; kk < BK; kk++) {
            float a[TM], w[TN];
            const float4 a0 = *reinterpret_cast<const float4*>(&As[cur][kk][ty * TM]);
            const float4 a1 = *reinterpret_cast<const float4*>(&As[cur][kk][ty * TM + 4]);
            a[0] = a0.x; a[1] = a0.y; a[2] = a0.z; a[3] = a0.w;
            a[4] = a1.x; a[5] = a1.y; a[6] = a1.z; a[7] = a1.w;
            const float4 w4 = *reinterpret_cast<const float4*>(&Ws[cur][kk][tx * TN]);
            w[0] = w4.x; w[1] = w4.y; w[2] = w4.z; w[3] = w4.w;
            #pragma unroll
            for (int i = 0; i < TM; i++)
                #pragma unroll
                for (int j = 0; j < TN; j++)
                    accv[i][j] = fmaf(a[i], w[j], accv[i][j]);
        }

        if (kt + 1 < KT) {
            sts((kt + 1) & 1);
            __syncthreads();
        }
    }

    // epilogue
    #pragma unroll
    for (int i = 0; i < TM; i++) {
        const int m = row0 + ty * TM + i;
        if (m >= M) continue;
        #pragma unroll
        for (int j = 0; j < TN; j++) {
            const int n = col0 + tx * TN + j;
            if (n >= N) continue;
            float v = accv[i][j];
            if (bias) v += bias[n];
            if (act == 1) v = 0.5f * v * (1.f + erff(v * 0.70710678118654752f)); // exact GELU
            else if (act == 2) v = tanhf(v);
            if (acc) C[(size_t)m * N + n] += v;
            else     C[(size_t)m * N + n]  = v;
        }
    }
}

// ---------------- row norms (D=128, one row per 128-thread block) ----------------
__global__ void rmsnorm_kernel(const float* __restrict__ in, const float* __restrict__ w,
                               float* __restrict__ out)
{
    const int row = blockIdx.x, d = threadIdx.x;
    const float v = in[row * D_ + d];
    float s = v * v;
    #pragma unroll
    for (int o = 16; o; o >>= 1) s += __shfl_xor_sync(0xffffffffu, s, o);
    __shared__ float sm[4];
    __shared__ float scale;
    if ((d & 31) == 0) sm[d >> 5] = s;
    __syncthreads();
    if (d == 0) scale = rsqrtf((sm[0] + sm[1] + sm[2] + sm[3]) * (1.f / D_) + EPSV);
    __syncthreads();
    out[row * D_ + d] = v * scale * w[d];
}

__global__ void layernorm_kernel(const float* __restrict__ in, const float* __restrict__ w,
                                 const float* __restrict__ b, float* __restrict__ out)
{
    const int row = blockIdx.x, d = threadIdx.x;
    const float v = in[row * D_ + d];
    float s = v, sq = v * v;
    #pragma unroll
    for (int o = 16; o; o >>= 1) {
        s  += __shfl_xor_sync(0xffffffffu, s,  o);
        sq += __shfl_xor_sync(0xffffffffu, sq, o);
    }
    __shared__ float sm0[4], sm1[4];
    __shared__ float mean, inv;
    if ((d & 31) == 0) { sm0[d >> 5] = s; sm1[d >> 5] = sq; }
    __syncthreads();
    if (d == 0) {
        float S = sm0[0] + sm0[1] + sm0[2] + sm0[3];
        float Q = sm1[0] + sm1[1] + sm1[2] + sm1[3];
        float m = S * (1.f / D_);
        float var = Q * (1.f / D_) - m * m;
        mean = m;
        inv = rsqrtf(var + EPSV);
    }
    __syncthreads();
    out[row * D_ + d] = (v - mean) * inv * w[d] + b[d];
}

// ---------------- depthwise causal conv (K=4) + silu ----------------
__global__ void conv_silu_kernel(const float* __restrict__ cw, const float* __restrict__ cb)
{
    const int t = blockIdx.x, e = threadIdx.x;
    float s = cb[e];
    #pragma unroll
    for (int j = 0; j < KC; j++) {
        int tt = t - (KC - 1) + j;
        if (tt >= 0) s = fmaf(g_xz[(size_t)tt * (2 * ED_) + e], cw[e * KC + j], s);
    }
    const float sg = 1.f / (1.f + __expf(-s));
    g_xc[(size_t)t * ED_ + e] = s * sg;
}

// ---------------- delta = softplus(dlt @ dt_w + dt_b) (K=8) ----------------
#define DTROWS 32
__global__ void dt_kernel(const float* __restrict__ dtw, const float* __restrict__ dtb)
{
    const int t0 = blockIdx.x * DTROWS;
    const int e = threadIdx.x;
    __shared__ float sd[DTROWS][DTD];
    for (int idx = e; idx < DTROWS * DTD; idx += ED_) {
        int r = idx >> 3, k = idx & 7;
        int t = t0 + r;
        sd[r][k] = (t < L) ? g_dbl[(size_t)t * 40 + k] : 0.f;
    }
    __syncthreads();
    float w[DTD];
    #pragma unroll
    for (int k = 0; k < DTD; k++) w[k] = dtw[k * ED_ + e];
    const float b = dtb[e];
    for (int r = 0; r < DTROWS; r++) {
        int t = t0 + r;
        if (t >= L) break;
        float s = b;
        #pragma unroll
        for (int k = 0; k < DTD; k++) s = fmaf(sd[r][k], w[k], s);
        float sp = (s > 0.f) ? (s + log1pf(__expf(-s))) : log1pf(__expf(s));
        g_delta[(size_t)t * ED_ + e] = sp;
    }
}

// ---------------- chunked selective scan ----------------
// phase 1: per-chunk (prod dA, local scan with h0=0)
__global__ void scan_pass1(const float* __restrict__ alog)
{
    const int e = threadIdx.x;            // 0..255
    const int chunk = blockIdx.x;
    const int t0 = chunk * LC;
    const int tend = min(t0 + LC, L);
    const int nt = tend - t0;

    __shared__ float sB[LC][NST];
    for (int idx = e; idx < nt * NST; idx += ED_) {
        int tt = idx >> 4, n = idx & 15;
        sB[tt][n] = g_dbl[(size_t)(t0 + tt) * 40 + DTD + n];
    }
    __syncthreads();

    float Areg[NST];
    #pragma unroll
    for (int n = 0; n < NST; n++) Areg[n] = -__expf(alog[e * NST + n]);

    float h[NST], ap[NST];
    #pragma unroll
    for (int n = 0; n < NST; n++) { h[n] = 0.f; ap[n] = 1.f; }

    for (int tt = 0; tt < nt; tt++) {
        const int t = t0 + tt;
        const float d = g_delta[(size_t)t * ED_ + e];
        const float x = g_xc[(size_t)t * ED_ + e];
        const float dx = d * x;
        #pragma unroll
        for (int n = 0; n < NST; n++) {
            const float a = __expf(d * Areg[n]);
            h[n] = fmaf(a, h[n], dx * sB[tt][n]);
            ap[n] *= a;
        }
    }
    const size_t base = (size_t)chunk * (ED_ * NST) + e * NST;
    #pragma unroll
    for (int n = 0; n < NST; n++) {
        g_Aprod[base + n] = ap[n];
        g_Bacc [base + n] = h[n];
    }
}

// phase 2: sequential combine over chunks, per channel (4096 channels)
__global__ void scan_pass2()
{
    const int c = blockIdx.x * blockDim.x + threadIdx.x;  // 0..4095
    float s = 0.f;
    for (int k = 0; k < CH; k++) {
        const size_t idx = (size_t)k * (ED_ * NST) + c;
        g_Hinit[idx] = s;
        s = fmaf(g_Aprod[idx], s, g_Bacc[idx]);
    }
}

// phase 3: replay with correct h0, fused D-skip + silu(z) gate -> g_y
__global__ void scan_pass3(const float* __restrict__ alog, const float* __restrict__ dp)
{
    const int e = threadIdx.x;
    const int chunk = blockIdx.x;
    const int t0 = chunk * LC;
    const int tend = min(t0 + LC, L);
    const int nt = tend - t0;
    if (nt <= 0) return;

    __shared__ float sB[LC][NST];
    __shared__ float sC[LC][NST];
    for (int idx = e; idx < nt * NST; idx += ED_) {
        int tt = idx >> 4, n = idx & 15;
        sB[tt][n] = g_dbl[(size_t)(t0 + tt) * 40 + DTD + n];
        sC[tt][n] = g_dbl[(size_t)(t0 + tt) * 40 + DTD + NST + n];
    }
    __syncthreads();

    float Areg[NST], h[NST];
    #pragma unroll
    for (int n = 0; n < NST; n++) Areg[n] = -__expf(alog[e * NST + n]);
    const size_t base = (size_t)chunk * (ED_ * NST) + e * NST;
    #pragma unroll
    for (int n = 0; n < NST; n++) h[n] = g_Hinit[base + n];

    const float dpe = dp[e];
    for (int tt = 0; tt < nt; tt++) {
        const int t = t0 + tt;
        const float d = g_delta[(size_t)t * ED_ + e];
        const float x = g_xc[(size_t)t * ED_ + e];
        const float dx = d * x;
        float y = 0.f;
        #pragma unroll
        for (int n = 0; n < NST; n++) {
            const float a = __expf(d * Areg[n]);
            h[n] = fmaf(a, h[n], dx * sB[tt][n]);
            y = fmaf(h[n], sC[tt][n], y);
        }
        y = fmaf(dpe, x, y);
        const float z = g_xz[(size_t)t * (2 * ED_) + ED_ + e];
        const float sg = 1.f / (1.f + __expf(-z));
        g_y[(size_t)t * ED_ + e] = y * (z * sg);
    }
}

// ---------------- attention score: a[t] = s1[t] . w2 + b2 ----------------
__global__ void att_score_kernel(const float* __restrict__ w2, const float* __restrict__ b2)
{
    const int row = blockIdx.x, d = threadIdx.x;  // 128 threads
    float v = g_xz[(size_t)row * D_ + d] * w2[d];
    #pragma unroll
    for (int o = 16; o; o >>= 1) v += __shfl_xor_sync(0xffffffffu, v, o);
    __shared__ float sm[4];
    if ((d & 31) == 0) sm[d >> 5] = v;
    __syncthreads();
    if (d == 0) g_att[row] = sm[0] + sm[1] + sm[2] + sm[3] + b2[0];
}

// ---------------- softmax over L (single block) ----------------
__global__ void softmax_kernel()
{
    const int tid = threadIdx.x;            // 1024 threads
    __shared__ float red[32];
    __shared__ float bmax, bsum;

    float m = -1e30f;
    for (int t = tid; t < L; t += 1024) m = fmaxf(m, g_att[t]);
    #pragma unroll
    for (int o = 16; o; o >>= 1) m = fmaxf(m, __shfl_xor_sync(0xffffffffu, m, o));
    if ((tid & 31) == 0) red[tid >> 5] = m;
    __syncthreads();
    if (tid < 32) {
        float v = red[tid];
        #pragma unroll
        for (int o = 16; o; o >>= 1) v = fmaxf(v, __shfl_xor_sync(0xffffffffu, v, o));
        if (tid == 0) bmax = v;
    }
    __syncthreads();
    const float mx = bmax;

    float s = 0.f;
    for (int t = tid; t < L; t += 1024) s += __expf(g_att[t] - mx);
    #pragma unroll
    for (int o = 16; o; o >>= 1) s += __shfl_xor_sync(0xffffffffu, s, o);
    __syncthreads();
    if ((tid & 31) == 0) red[tid >> 5] = s;
    __syncthreads();
    if (tid < 32) {
        float v = red[tid];
        #pragma unroll
        for (int o = 16; o; o >>= 1) v += __shfl_xor_sync(0xffffffffu, v, o);
        if (tid == 0) bsum = v;
    }
    __syncthreads();
    const float inv = 1.f / bsum;
    for (int t = tid; t < L; t += 1024) g_att[t] = __expf(g_att[t] - mx) * inv;
}

// ---------------- pooled = sum_t att[t] * h[t,:] (two-stage deterministic) ----------------
__global__ void pooled_part_kernel()
{
    const int b = blockIdx.x, d = threadIdx.x;   // PB blocks x 128 threads
    const int per = (L + PB - 1) / PB;
    const int t0 = b * per, t1 = min(t0 + per, L);
    float s = 0.f;
    for (int t = t0; t < t1; t++) s = fmaf(g_att[t], g_hn[(size_t)t * D_ + d], s);
    g_part[b * D_ + d] = s;
}

__global__ void final_kernel(const float* __restrict__ cls_w, const float* __restrict__ cls_b,
                             float* __restrict__ out, int out_size)
{
    const int d = threadIdx.x;  // 128
    float p = 0.f;
    for (int b = 0; b < PB; b++) p += g_part[b * D_ + d];
    float c0 = p * cls_w[d * 2 + 0];
    float c1 = p * cls_w[d * 2 + 1];
    #pragma unroll
    for (int o = 16; o; o >>= 1) {
        c0 += __shfl_xor_sync(0xffffffffu, c0, o);
        c1 += __shfl_xor_sync(0xffffffffu, c1, o);
    }
    __shared__ float s0[4], s1[4];
    if ((d & 31) == 0) { s0[d >> 5] = c0; s1[d >> 5] = c1; }
    __syncthreads();
    if (d == 0) {
        const float l0 = s0[0] + s0[1] + s0[2] + s0[3] + cls_b[0];
        const float l1 = s1[0] + s1[1] + s1[2] + s1[3] + cls_b[1];
        const float mx = fmaxf(l0, l1);
        const float e0 = expf(l0 - mx), e1 = expf(l1 - mx);
        const float den = e0 + e1;
        const float p0 = e0 / den, p1 = e1 / den;
        const float hat = (l1 > l0) ? 1.f : 0.f;
        if (out_size >= 1) out[0] = l0;
        if (out_size >= 2) out[1] = l1;
        if (out_size >= 3) out[2] = p0;
        if (out_size >= 4) out[3] = p1;
        if (out_size >= 5) out[4] = hat;
        for (int i = 5; i < out_size; i++) out[i] = 0.f;
    }
}

// ---------------- host orchestration ----------------
extern "C" void kernel_launch(void* const* d_in, const int* in_sizes, int n_in,
                              void* d_out, int out_size)
{
    const float* x        = (const float*)d_in[0];
    // d_in[1] = coords (unused by reference)
    const float* fc1_w    = (const float*)d_in[2];
    const float* fc1_b    = (const float*)d_in[3];
    const float* rms_w    = (const float*)d_in[4];
    const float* inproj_w = (const float*)d_in[5];
    const float* conv_w   = (const float*)d_in[6];
    const float* conv_b   = (const float*)d_in[7];
    const float* xproj_w  = (const float*)d_in[8];
    const float* dt_w     = (const float*)d_in[9];
    const float* dt_b     = (const float*)d_in[10];
    const float* A_log    = (const float*)d_in[11];
    const float* D_p      = (const float*)d_in[12];
    const float* outproj_w= (const float*)d_in[13];
    const float* ln_w     = (const float*)d_in[14];
    const float* ln_b     = (const float*)d_in[15];
    const float* att_w1   = (const float*)d_in[16];
    const float* att_b1   = (const float*)d_in[17];
    const float* att_w2   = (const float*)d_in[18];
    const float* att_b2   = (const float*)d_in[19];
    const float* cls_w    = (const float*)d_in[20];
    const float* cls_b    = (const float*)d_in[21];
    float* out = (float*)d_out;

    float *p_h, *p_hn, *p_xz, *p_xc, *p_dbl, *p_y;
    cudaGetSymbolAddress((void**)&p_h,  g_h);
    cudaGetSymbolAddress((void**)&p_hn, g_hn);
    cudaGetSymbolAddress((void**)&p_xz, g_xz);
    cudaGetSymbolAddress((void**)&p_xc, g_xc);
    cudaGetSymbolAddress((void**)&p_dbl,g_dbl);
    cudaGetSymbolAddress((void**)&p_y,  g_y);

    const int MT = (L + BM - 1) / BM;   // 94 row tiles of 128

    // 1) h = gelu(x @ fc1_w + fc1_b)
    gemm_kernel<<<dim3(D_ / BN, MT), 256>>>(x, fc1_w, fc1_b, p_h,
                                            L, IN_, D_, /*gelu*/1, 0);

    for (int layer = 0; layer < NLAY; layer++) {
        const float* ipw  = inproj_w  + (size_t)layer * D_ * 2 * ED_;
        const float* cw   = conv_w    + (size_t)layer * ED_ * KC;
        const float* cb   = conv_b    + (size_t)layer * ED_;
        const float* xpw  = xproj_w   + (size_t)layer * ED_ * 40;
        const float* dtw  = dt_w      + (size_t)layer * DTD * ED_;
        const float* dtb  = dt_b      + (size_t)layer * ED_;
        const float* alog = A_log     + (size_t)layer * ED_ * NST;
        const float* dp   = D_p       + (size_t)layer * ED_;
        const float* opw  = outproj_w + (size_t)layer * ED_ * D_;
        const float* rw   = rms_w     + (size_t)layer * D_;

        // hn = rmsnorm(h)
        rmsnorm_kernel<<<L, D_>>>(p_h, rw, p_hn);
        // xz = hn @ inproj  (L x 512)
        gemm_kernel<<<dim3((2 * ED_) / BN, MT), 256>>>(p_hn, ipw, nullptr, p_xz,
                                                       L, D_, 2 * ED_, 0, 0);
        // xc = silu(causal_conv(xb))
        conv_silu_kernel<<<L, ED_>>>(cw, cb);
        // dbl = xc @ xproj (L x 40)
        gemm_kernel<<<dim3(1, MT), 256>>>(p_xc, xpw, nullptr, p_dbl,
                                          L, ED_, 40, 0, 0);
        // delta = softplus(dlt @ dt_w + dt_b)
        dt_kernel<<<(L + DTROWS - 1) / DTROWS, ED_>>>(dtw, dtb);
        // chunked scan
        scan_pass1<<<CH, ED_>>>(alog);
        scan_pass2<<<16, 256>>>();
        scan_pass3<<<CH, ED_>>>(alog, dp);
        // h += y @ outproj
        gemm_kernel<<<dim3(D_ / BN, MT), 256>>>(p_y, opw, nullptr, p_h,
                                                L, ED_, D_, 0, /*acc*/1);
    }

    // final layernorm -> hn
    layernorm_kernel<<<L, D_>>>(p_h, ln_w, ln_b, p_hn);
    // s1 = tanh(hn @ att_w1 + b1) -> reuse g_xz (stride 128)
    gemm_kernel<<<dim3(128 / BN, MT), 256>>>(p_hn, att_w1, att_b1, p_xz,
                                             L, D_, 128, /*tanh*/2, 0);
    att_score_kernel<<<L, D_>>>(att_w2, att_b2);
    softmax_kernel<<<1, 1024>>>();
    pooled_part_kernel<<<PB, D_>>>();
    final_kernel<<<1, D_>>>(cls_w, cls_b, out, out_size);
}

// round 13
// speedup vs baseline: 1.2560x; 1.1028x over previous
#include <cuda_runtime.h>
#include <math.h>

// ---------------- problem constants ----------------
#define L    12000
#define IN_  1024
#define D_   128
#define ED_  256
#define NST  16
#define DTD  8
#define KC   4
#define NLAY 2
#define EPSV 1e-5f

// chunked scan config: 296 chunks of 41 (296 = 2*148 SMs)
#define CH  296
#define LC  41

// pooled partial blocks
#define PB  96

// ---------------- device scratch (static, no allocation) ----------------
__device__ float g_h    [L * D_];        // residual stream
__device__ float g_hn   [L * D_];        // normed stream
__device__ float g_xz   [L * 2 * ED_];   // inproj out (xb | z); reused for att hidden
__device__ float g_xc   [L * ED_];       // conv+silu out
__device__ float g_dbl  [L * 40];        // xproj out (dlt | B | C)
__device__ float g_delta[L * ED_];       // softplus(dt)
__device__ float g_y    [L * ED_];       // scan output (gated)
__device__ float g_Aprod[CH * ED_ * NST];
__device__ float g_Bacc [CH * ED_ * NST];
__device__ float g_Hinit[CH * ED_ * NST];
__device__ float g_att  [L];
__device__ float g_part [PB * D_];

// ---------------- TF32 tensor-core SGEMM ----------------
// C[M,N] = act(A[M,K] @ W[K,N] (+bias)), optional +=
// Block tile 128x64, 8 warps (4x2), warp tile 32x32 = (2x4) m16n8k8 mma tiles.
#define BM 128
#define BN 64
#define BK 16

__device__ __forceinline__ float f2tf32(float x) {
    unsigned u;
    asm("cvt.rna.tf32.f32 %0, %1;" : "=r"(u) : "f"(x));
    return __uint_as_float(u);
}

__device__ __forceinline__ void mma_tf32(float* c, const unsigned* a, const unsigned* b) {
    asm volatile(
        "mma.sync.aligned.m16n8k8.row.col.f32.tf32.tf32.f32 "
        "{%0,%1,%2,%3}, {%4,%5,%6,%7}, {%8,%9}, {%0,%1,%2,%3};\n"
        : "+f"(c[0]), "+f"(c[1]), "+f"(c[2]), "+f"(c[3])
        : "r"(a[0]), "r"(a[1]), "r"(a[2]), "r"(a[3]), "r"(b[0]), "r"(b[1]));
}

__global__ __launch_bounds__(256, 2)
void gemm_tc_kernel(const float* __restrict__ A, const float* __restrict__ W,
                    const float* __restrict__ bias, float* __restrict__ C,
                    int M, int K, int N, int act, int acc)
{
    __shared__ float As[2][BK][BM + 4];   // [k][m], pad 4 -> conflict-free frag reads
    __shared__ float Ws[2][BK][BN + 8];   // [k][n], pad 8

    const int tid  = threadIdx.x;
    const int lane = tid & 31;
    const int wid  = tid >> 5;            // 0..7
    const int warp_m = wid & 3;           // 4 warps along M
    const int warp_n = wid >> 2;          // 2 warps along N
    const int lq = lane >> 2;             // groupID   (0..7)
    const int lr = lane & 3;              // threadID_in_group (0..3)

    const int row0 = blockIdx.y * BM;
    const int col0 = blockIdx.x * BN;

    float accf[2][4][4];
    #pragma unroll
    for (int mi = 0; mi < 2; mi++)
        #pragma unroll
        for (int nj = 0; nj < 4; nj++)
            #pragma unroll
            for (int q = 0; q < 4; q++) accf[mi][nj][q] = 0.f;

    // A tile: 128x16 = 512 float4 -> 2/thread: f = tid + p*256; r=f>>2, kq=f&3
    // W tile: 16x64  = 256 float4 -> 1/thread: k = tid>>4, nq = tid&15
    float4 aldg[2], wldg;

    auto ldgA = [&](int k0) {
        #pragma unroll
        for (int p = 0; p < 2; p++) {
            const int f = tid + p * 256;
            const int r = f >> 2;
            const int kq = f & 3;
            const int gr = row0 + r;
            if (gr < M)
                aldg[p] = *reinterpret_cast<const float4*>(&A[(size_t)gr * K + k0 + kq * 4]);
            else
                aldg[p] = make_float4(0.f, 0.f, 0.f, 0.f);
        }
    };
    auto ldgW = [&](int k0) {
        const int k  = tid >> 4;
        const int nq = tid & 15;
        const int gn0 = col0 + nq * 4;
        if (gn0 + 3 < N) {
            wldg = *reinterpret_cast<const float4*>(&W[(size_t)(k0 + k) * N + gn0]);
        } else {
            float v[4];
            #pragma unroll
            for (int j = 0; j < 4; j++)
                v[j] = (gn0 + j < N) ? W[(size_t)(k0 + k) * N + gn0 + j] : 0.f;
            wldg = make_float4(v[0], v[1], v[2], v[3]);
        }
    };
    auto sts = [&](int buf) {
        #pragma unroll
        for (int p = 0; p < 2; p++) {
            const int f = tid + p * 256;
            const int r = f >> 2;
            const int kq = f & 3;
            As[buf][kq * 4 + 0][r] = f2tf32(aldg[p].x);
            As[buf][kq * 4 + 1][r] = f2tf32(aldg[p].y);
            As[buf][kq * 4 + 2][r] = f2tf32(aldg[p].z);
            As[buf][kq * 4 + 3][r] = f2tf32(aldg[p].w);
        }
        const int k  = tid >> 4;
        const int nq = tid & 15;
        Ws[buf][k][nq * 4 + 0] = f2tf32(wldg.x);
        Ws[buf][k][nq * 4 + 1] = f2tf32(wldg.y);
        Ws[buf][k][nq * 4 + 2] = f2tf32(wldg.z);
        Ws[buf][k][nq * 4 + 3] = f2tf32(wldg.w);
    };

    // prologue
    ldgA(0); ldgW(0);
    sts(0);
    __syncthreads();

    const int KT = K / BK;
    for (int kt = 0; kt < KT; kt++) {
        const int cur = kt & 1;
        if (kt + 1 < KT) { ldgA((kt + 1) * BK); ldgW((kt + 1) * BK); }

        #pragma unroll
        for (int step = 0; step < 2; step++) {     // two k=8 slices per BK=16
            const int kb = step * 8;
            unsigned afr[2][4];
            #pragma unroll
            for (int mi = 0; mi < 2; mi++) {
                const int mb = warp_m * 32 + mi * 16 + lq;
                afr[mi][0] = __float_as_uint(As[cur][kb + lr    ][mb    ]);
                afr[mi][1] = __float_as_uint(As[cur][kb + lr    ][mb + 8]);
                afr[mi][2] = __float_as_uint(As[cur][kb + lr + 4][mb    ]);
                afr[mi][3] = __float_as_uint(As[cur][kb + lr + 4][mb + 8]);
            }
            unsigned bfr[4][2];
            #pragma unroll
            for (int nj = 0; nj < 4; nj++) {
                const int nb = warp_n * 32 + nj * 8 + lq;
                bfr[nj][0] = __float_as_uint(Ws[cur][kb + lr    ][nb]);
                bfr[nj][1] = __float_as_uint(Ws[cur][kb + lr + 4][nb]);
            }
            #pragma unroll
            for (int mi = 0; mi < 2; mi++)
                #pragma unroll
                for (int nj = 0; nj < 4; nj++)
                    mma_tf32(accf[mi][nj], afr[mi], bfr[nj]);
        }

        if (kt + 1 < KT) {
            sts((kt + 1) & 1);
            __syncthreads();
        }
    }

    // epilogue: c0,c1 at (row, 2*lr), (row, 2*lr+1); c2,c3 at row+8
    #pragma unroll
    for (int mi = 0; mi < 2; mi++) {
        #pragma unroll
        for (int nj = 0; nj < 4; nj++) {
            const int mbase = row0 + warp_m * 32 + mi * 16 + lq;
            const int nbase = col0 + warp_n * 32 + nj * 8 + 2 * lr;
            #pragma unroll
            for (int half = 0; half < 2; half++) {
                const int m = mbase + half * 8;
                if (m >= M) continue;
                #pragma unroll
                for (int q = 0; q < 2; q++) {
                    const int n = nbase + q;
                    if (n >= N) continue;
                    float v = accf[mi][nj][half * 2 + q];
                    if (bias) v += bias[n];
                    if (act == 1) v = 0.5f * v * (1.f + erff(v * 0.70710678118654752f));
                    else if (act == 2) v = tanhf(v);
                    if (acc) C[(size_t)m * N + n] += v;
                    else     C[(size_t)m * N + n]  = v;
                }
            }
        }
    }
}

// ---------------- row norms (D=128, one row per 128-thread block) ----------------
__global__ void rmsnorm_kernel(const float* __restrict__ in, const float* __restrict__ w,
                               float* __restrict__ out)
{
    const int row = blockIdx.x, d = threadIdx.x;
    const float v = in[row * D_ + d];
    float s = v * v;
    #pragma unroll
    for (int o = 16; o; o >>= 1) s += __shfl_xor_sync(0xffffffffu, s, o);
    __shared__ float sm[4];
    __shared__ float scale;
    if ((d & 31) == 0) sm[d >> 5] = s;
    __syncthreads();
    if (d == 0) scale = rsqrtf((sm[0] + sm[1] + sm[2] + sm[3]) * (1.f / D_) + EPSV);
    __syncthreads();
    out[row * D_ + d] = v * scale * w[d];
}

__global__ void layernorm_kernel(const float* __restrict__ in, const float* __restrict__ w,
                                 const float* __restrict__ b, float* __restrict__ out)
{
    const int row = blockIdx.x, d = threadIdx.x;
    const float v = in[row * D_ + d];
    float s = v, sq = v * v;
    #pragma unroll
    for (int o = 16; o; o >>= 1) {
        s  += __shfl_xor_sync(0xffffffffu, s,  o);
        sq += __shfl_xor_sync(0xffffffffu, sq, o);
    }
    __shared__ float sm0[4], sm1[4];
    __shared__ float mean, inv;
    if ((d & 31) == 0) { sm0[d >> 5] = s; sm1[d >> 5] = sq; }
    __syncthreads();
    if (d == 0) {
        float S = sm0[0] + sm0[1] + sm0[2] + sm0[3];
        float Q = sm1[0] + sm1[1] + sm1[2] + sm1[3];
        float m = S * (1.f / D_);
        float var = Q * (1.f / D_) - m * m;
        mean = m;
        inv = rsqrtf(var + EPSV);
    }
    __syncthreads();
    out[row * D_ + d] = (v - mean) * inv * w[d] + b[d];
}

// ---------------- depthwise causal conv (K=4) + silu ----------------
__global__ void conv_silu_kernel(const float* __restrict__ cw, const float* __restrict__ cb)
{
    const int t = blockIdx.x, e = threadIdx.x;
    float s = cb[e];
    #pragma unroll
    for (int j = 0; j < KC; j++) {
        int tt = t - (KC - 1) + j;
        if (tt >= 0) s = fmaf(g_xz[(size_t)tt * (2 * ED_) + e], cw[e * KC + j], s);
    }
    const float sg = 1.f / (1.f + __expf(-s));
    g_xc[(size_t)t * ED_ + e] = s * sg;
}

// ---------------- delta = softplus(dlt @ dt_w + dt_b) (K=8) ----------------
#define DTROWS 32
__global__ void dt_kernel(const float* __restrict__ dtw, const float* __restrict__ dtb)
{
    const int t0 = blockIdx.x * DTROWS;
    const int e = threadIdx.x;
    __shared__ float sd[DTROWS][DTD];
    for (int idx = e; idx < DTROWS * DTD; idx += ED_) {
        int r = idx >> 3, k = idx & 7;
        int t = t0 + r;
        sd[r][k] = (t < L) ? g_dbl[(size_t)t * 40 + k] : 0.f;
    }
    __syncthreads();
    float w[DTD];
    #pragma unroll
    for (int k = 0; k < DTD; k++) w[k] = dtw[k * ED_ + e];
    const float b = dtb[e];
    for (int r = 0; r < DTROWS; r++) {
        int t = t0 + r;
        if (t >= L) break;
        float s = b;
        #pragma unroll
        for (int k = 0; k < DTD; k++) s = fmaf(sd[r][k], w[k], s);
        float sp = (s > 0.f) ? (s + log1pf(__expf(-s))) : log1pf(__expf(s));
        g_delta[(size_t)t * ED_ + e] = sp;
    }
}

// ---------------- chunked selective scan ----------------
// phase 1: per-chunk (prod dA, local scan with h0=0)
__global__ void scan_pass1(const float* __restrict__ alog)
{
    const int e = threadIdx.x;            // 0..255
    const int chunk = blockIdx.x;
    const int t0 = chunk * LC;
    const int tend = min(t0 + LC, L);
    const int nt = tend - t0;

    __shared__ float sB[LC][NST];
    for (int idx = e; idx < nt * NST; idx += ED_) {
        int tt = idx >> 4, n = idx & 15;
        sB[tt][n] = g_dbl[(size_t)(t0 + tt) * 40 + DTD + n];
    }
    __syncthreads();

    float Areg[NST];
    #pragma unroll
    for (int n = 0; n < NST; n++) Areg[n] = -__expf(alog[e * NST + n]);

    float h[NST], ap[NST];
    #pragma unroll
    for (int n = 0; n < NST; n++) { h[n] = 0.f; ap[n] = 1.f; }

    for (int tt = 0; tt < nt; tt++) {
        const int t = t0 + tt;
        const float d = g_delta[(size_t)t * ED_ + e];
        const float x = g_xc[(size_t)t * ED_ + e];
        const float dx = d * x;
        #pragma unroll
        for (int n = 0; n < NST; n++) {
            const float a = __expf(d * Areg[n]);
            h[n] = fmaf(a, h[n], dx * sB[tt][n]);
            ap[n] *= a;
        }
    }
    const size_t base = (size_t)chunk * (ED_ * NST) + e * NST;
    #pragma unroll
    for (int n = 0; n < NST; n++) {
        g_Aprod[base + n] = ap[n];
        g_Bacc [base + n] = h[n];
    }
}

// phase 2: sequential combine over chunks, per channel (4096 channels)
__global__ void scan_pass2()
{
    const int c = blockIdx.x * blockDim.x + threadIdx.x;  // 0..4095
    float s = 0.f;
    for (int k = 0; k < CH; k++) {
        const size_t idx = (size_t)k * (ED_ * NST) + c;
        g_Hinit[idx] = s;
        s = fmaf(g_Aprod[idx], s, g_Bacc[idx]);
    }
}

// phase 3: replay with correct h0, fused D-skip + silu(z) gate -> g_y
__global__ void scan_pass3(const float* __restrict__ alog, const float* __restrict__ dp)
{
    const int e = threadIdx.x;
    const int chunk = blockIdx.x;
    const int t0 = chunk * LC;
    const int tend = min(t0 + LC, L);
    const int nt = tend - t0;
    if (nt <= 0) return;

    __shared__ float sB[LC][NST];
    __shared__ float sC[LC][NST];
    for (int idx = e; idx < nt * NST; idx += ED_) {
        int tt = idx >> 4, n = idx & 15;
        sB[tt][n] = g_dbl[(size_t)(t0 + tt) * 40 + DTD + n];
        sC[tt][n] = g_dbl[(size_t)(t0 + tt) * 40 + DTD + NST + n];
    }
    __syncthreads();

    float Areg[NST], h[NST];
    #pragma unroll
    for (int n = 0; n < NST; n++) Areg[n] = -__expf(alog[e * NST + n]);
    const size_t base = (size_t)chunk * (ED_ * NST) + e * NST;
    #pragma unroll
    for (int n = 0; n < NST; n++) h[n] = g_Hinit[base + n];

    const float dpe = dp[e];
    for (int tt = 0; tt < nt; tt++) {
        const int t = t0 + tt;
        const float d = g_delta[(size_t)t * ED_ + e];
        const float x = g_xc[(size_t)t * ED_ + e];
        const float dx = d * x;
        float y = 0.f;
        #pragma unroll
        for (int n = 0; n < NST; n++) {
            const float a = __expf(d * Areg[n]);
            h[n] = fmaf(a, h[n], dx * sB[tt][n]);
            y = fmaf(h[n], sC[tt][n], y);
        }
        y = fmaf(dpe, x, y);
        const float z = g_xz[(size_t)t * (2 * ED_) + ED_ + e];
        const float sg = 1.f / (1.f + __expf(-z));
        g_y[(size_t)t * ED_ + e] = y * (z * sg);
    }
}

// ---------------- attention score: a[t] = s1[t] . w2 + b2 ----------------
__global__ void att_score_kernel(const float* __restrict__ w2, const float* __restrict__ b2)
{
    const int row = blockIdx.x, d = threadIdx.x;  // 128 threads
    float v = g_xz[(size_t)row * D_ + d] * w2[d];
    #pragma unroll
    for (int o = 16; o; o >>= 1) v += __shfl_xor_sync(0xffffffffu, v, o);
    __shared__ float sm[4];
    if ((d & 31) == 0) sm[d >> 5] = v;
    __syncthreads();
    if (d == 0) g_att[row] = sm[0] + sm[1] + sm[2] + sm[3] + b2[0];
}

// ---------------- softmax over L (single block) ----------------
__global__ void softmax_kernel()
{
    const int tid = threadIdx.x;            // 1024 threads
    __shared__ float red[32];
    __shared__ float bmax, bsum;

    float m = -1e30f;
    for (int t = tid; t < L; t += 1024) m = fmaxf(m, g_att[t]);
    #pragma unroll
    for (int o = 16; o; o >>= 1) m = fmaxf(m, __shfl_xor_sync(0xffffffffu, m, o));
    if ((tid & 31) == 0) red[tid >> 5] = m;
    __syncthreads();
    if (tid < 32) {
        float v = red[tid];
        #pragma unroll
        for (int o = 16; o; o >>= 1) v = fmaxf(v, __shfl_xor_sync(0xffffffffu, v, o));
        if (tid == 0) bmax = v;
    }
    __syncthreads();
    const float mx = bmax;

    float s = 0.f;
    for (int t = tid; t < L; t += 1024) s += __expf(g_att[t] - mx);
    #pragma unroll
    for (int o = 16; o; o >>= 1) s += __shfl_xor_sync(0xffffffffu, s, o);
    __syncthreads();
    if ((tid & 31) == 0) red[tid >> 5] = s;
    __syncthreads();
    if (tid < 32) {
        float v = red[tid];
        #pragma unroll
        for (int o = 16; o; o >>= 1) v += __shfl_xor_sync(0xffffffffu, v, o);
        if (tid == 0) bsum = v;
    }
    __syncthreads();
    const float inv = 1.f / bsum;
    for (int t = tid; t < L; t += 1024) g_att[t] = __expf(g_att[t] - mx) * inv;
}

// ---------------- pooled = sum_t att[t] * h[t,:] (two-stage deterministic) ----------------
__global__ void pooled_part_kernel()
{
    const int b = blockIdx.x, d = threadIdx.x;   // PB blocks x 128 threads
    const int per = (L + PB - 1) / PB;
    const int t0 = b * per, t1 = min(t0 + per, L);
    float s = 0.f;
    for (int t = t0; t < t1; t++) s = fmaf(g_att[t], g_hn[(size_t)t * D_ + d], s);
    g_part[b * D_ + d] = s;
}

__global__ void final_kernel(const float* __restrict__ cls_w, const float* __restrict__ cls_b,
                             float* __restrict__ out, int out_size)
{
    const int d = threadIdx.x;  // 128
    float p = 0.f;
    for (int b = 0; b < PB; b++) p += g_part[b * D_ + d];
    float c0 = p * cls_w[d * 2 + 0];
    float c1 = p * cls_w[d * 2 + 1];
    #pragma unroll
    for (int o = 16; o; o >>= 1) {
        c0 += __shfl_xor_sync(0xffffffffu, c0, o);
        c1 += __shfl_xor_sync(0xffffffffu, c1, o);
    }
    __shared__ float s0[4], s1[4];
    if ((d & 31) == 0) { s0[d >> 5] = c0; s1[d >> 5] = c1; }
    __syncthreads();
    if (d == 0) {
        const float l0 = s0[0] + s0[1] + s0[2] + s0[3] + cls_b[0];
        const float l1 = s1[0] + s1[1] + s1[2] + s1[3] + cls_b[1];
        const float mx = fmaxf(l0, l1);
        const float e0 = expf(l0 - mx), e1 = expf(l1 - mx);
        const float den = e0 + e1;
        const float p0 = e0 / den, p1 = e1 / den;
        const float hat = (l1 > l0) ? 1.f : 0.f;
        if (out_size >= 1) out[0] = l0;
        if (out_size >= 2) out[1] = l1;
        if (out_size >= 3) out[2] = p0;
        if (out_size >= 4) out[3] = p1;
        if (out_size >= 5) out[4] = hat;
        for (int i = 5; i < out_size; i++) out[i] = 0.f;
    }
}

// ---------------- host orchestration ----------------
extern "C" void kernel_launch(void* const* d_in, const int* in_sizes, int n_in,
                              void* d_out, int out_size)
{
    const float* x        = (const float*)d_in[0];
    // d_in[1] = coords (unused by reference)
    const float* fc1_w    = (const float*)d_in[2];
    const float* fc1_b    = (const float*)d_in[3];
    const float* rms_w    = (const float*)d_in[4];
    const float* inproj_w = (const float*)d_in[5];
    const float* conv_w   = (const float*)d_in[6];
    const float* conv_b   = (const float*)d_in[7];
    const float* xproj_w  = (const float*)d_in[8];
    const float* dt_w     = (const float*)d_in[9];
    const float* dt_b     = (const float*)d_in[10];
    const float* A_log    = (const float*)d_in[11];
    const float* D_p      = (const float*)d_in[12];
    const float* outproj_w= (const float*)d_in[13];
    const float* ln_w     = (const float*)d_in[14];
    const float* ln_b     = (const float*)d_in[15];
    const float* att_w1   = (const float*)d_in[16];
    const float* att_b1   = (const float*)d_in[17];
    const float* att_w2   = (const float*)d_in[18];
    const float* att_b2   = (const float*)d_in[19];
    const float* cls_w    = (const float*)d_in[20];
    const float* cls_b    = (const float*)d_in[21];
    float* out = (float*)d_out;

    float *p_h, *p_hn, *p_xz, *p_xc, *p_dbl, *p_y;
    cudaGetSymbolAddress((void**)&p_h,  g_h);
    cudaGetSymbolAddress((void**)&p_hn, g_hn);
    cudaGetSymbolAddress((void**)&p_xz, g_xz);
    cudaGetSymbolAddress((void**)&p_xc, g_xc);
    cudaGetSymbolAddress((void**)&p_dbl,g_dbl);
    cudaGetSymbolAddress((void**)&p_y,  g_y);

    const int MT = (L + BM - 1) / BM;   // 94 row tiles of 128

    // 1) h = gelu(x @ fc1_w + fc1_b)
    gemm_tc_kernel<<<dim3(D_ / BN, MT), 256>>>(x, fc1_w, fc1_b, p_h,
                                               L, IN_, D_, /*gelu*/1, 0);

    for (int layer = 0; layer < NLAY; layer++) {
        const float* ipw  = inproj_w  + (size_t)layer * D_ * 2 * ED_;
        const float* cw   = conv_w    + (size_t)layer * ED_ * KC;
        const float* cb   = conv_b    + (size_t)layer * ED_;
        const float* xpw  = xproj_w   + (size_t)layer * ED_ * 40;
        const float* dtw  = dt_w      + (size_t)layer * DTD * ED_;
        const float* dtb  = dt_b      + (size_t)layer * ED_;
        const float* alog = A_log     + (size_t)layer * ED_ * NST;
        const float* dp   = D_p       + (size_t)layer * ED_;
        const float* opw  = outproj_w + (size_t)layer * ED_ * D_;
        const float* rw   = rms_w     + (size_t)layer * D_;

        // hn = rmsnorm(h)
        rmsnorm_kernel<<<L, D_>>>(p_h, rw, p_hn);
        // xz = hn @ inproj  (L x 512)
        gemm_tc_kernel<<<dim3((2 * ED_) / BN, MT), 256>>>(p_hn, ipw, nullptr, p_xz,
                                                          L, D_, 2 * ED_, 0, 0);
        // xc = silu(causal_conv(xb))
        conv_silu_kernel<<<L, ED_>>>(cw, cb);
        // dbl = xc @ xproj (L x 40)
        gemm_tc_kernel<<<dim3(1, MT), 256>>>(p_xc, xpw, nullptr, p_dbl,
                                             L, ED_, 40, 0, 0);
        // delta = softplus(dlt @ dt_w + dt_b)
        dt_kernel<<<(L + DTROWS - 1) / DTROWS, ED_>>>(dtw, dtb);
        // chunked scan
        scan_pass1<<<CH, ED_>>>(alog);
        scan_pass2<<<16, 256>>>();
        scan_pass3<<<CH, ED_>>>(alog, dp);
        // h += y @ outproj
        gemm_tc_kernel<<<dim3(D_ / BN, MT), 256>>>(p_y, opw, nullptr, p_h,
                                                   L, ED_, D_, 0, /*acc*/1);
    }

    // final layernorm -> hn
    layernorm_kernel<<<L, D_>>>(p_h, ln_w, ln_b, p_hn);
    // s1 = tanh(hn @ att_w1 + b1) -> reuse g_xz (stride 128)
    gemm_tc_kernel<<<dim3(128 / BN, MT), 256>>>(p_hn, att_w1, att_b1, p_xz,
                                                L, D_, 128, /*tanh*/2, 0);
    att_score_kernel<<<L, D_>>>(att_w2, att_b2);
    softmax_kernel<<<1, 1024>>>();
    pooled_part_kernel<<<PB, D_>>>();
    final_kernel<<<1, D_>>>(cls_w, cls_b, out, out_size);
}